// round 6
// baseline (speedup 1.0000x reference)
#include <cuda_runtime.h>
#include <math.h>

#define DIM      256
#define NSEG     32768
#define RPI      4          // rows per iteration (8 independent LDG.128/thread)
#define WPB      4          // warps per block (small -> fast resource retirement)

// Allocation-free scratch: segment start offsets (batch is sorted).
__device__ int g_seg_start[NSEG + 1];

// Vectorized boundary scan: thread owns 4 consecutive batch entries (int4).
__global__ void seg_bounds_scan4(const int4* __restrict__ batch4,
                                 const int*  __restrict__ batch, int V) {
    int i = blockIdx.x * blockDim.x + threadIdx.x;
    int base = i * 4;
    if (base >= V) return;
    int4 c = batch4[i];
    int prev = (base == 0) ? -1 : batch[base - 1];
    for (int b = prev + 1; b <= c.x; ++b) g_seg_start[b] = base;
    for (int b = c.x  + 1; b <= c.y; ++b) g_seg_start[b] = base + 1;
    for (int b = c.y  + 1; b <= c.z; ++b) g_seg_start[b] = base + 2;
    for (int b = c.z  + 1; b <= c.w; ++b) g_seg_start[b] = base + 3;
    if (base + 4 >= V) {
        for (int b = c.w + 1; b <= NSEG; ++b) g_seg_start[b] = V;
    }
}

// One WARP per segment, single pass over H with online softmax.
// Register-pressure fix: only the h0 half of each row stays in registers
// across the score reduction; the h1 half is loaded with default caching
// (L1-resident) and RELOADED from L1 in the accumulate phase. This cuts
// live registers by ~16 -> higher occupancy to hide the serial shfl/exp
// spine. h0 uses __ldcs (read once, keep L2 clean).
__global__ __launch_bounds__(32 * WPB)
void agg_warp_kernel(const float4* __restrict__ H4,
                     const float4* __restrict__ Ww4,
                     const float*  __restrict__ Wb,
                     float4*       __restrict__ out4) {
    const int lane = threadIdx.x & 31;
    const int b    = blockIdx.x * WPB + (threadIdx.x >> 5);

    const int start = g_seg_start[b];
    const int end   = g_seg_start[b + 1];

    const float4 w0   = Ww4[lane];
    const float4 w1   = Ww4[lane + 32];
    const float  bias = Wb[0];

    float4 acc0 = make_float4(0.f, 0.f, 0.f, 0.f);
    float4 acc1 = make_float4(0.f, 0.f, 0.f, 0.f);
    float  m    = -INFINITY;
    float  ssum = 0.0f;

    int pos = start;

    // ---- guard-free main loop: full RPI rows ----
    for (; pos + RPI <= end; pos += RPI) {
        float4 h0[RPI];
        float  s[RPI];
        #pragma unroll
        for (int i = 0; i < RPI; ++i) {
            const float4* row = H4 + (long)(pos + i) * (DIM / 4);
            h0[i] = __ldcs(row + lane);        // retained in regs
            float4 h1 = row[lane + 32];        // default: stays in L1
            float d = h0[i].x * w0.x;
            d = fmaf(h0[i].y, w0.y, d);
            d = fmaf(h0[i].z, w0.z, d);
            d = fmaf(h0[i].w, w0.w, d);
            d = fmaf(h1.x, w1.x, d);
            d = fmaf(h1.y, w1.y, d);
            d = fmaf(h1.z, w1.z, d);
            d = fmaf(h1.w, w1.w, d);
            s[i] = d;
        }
        #pragma unroll
        for (int o = 16; o > 0; o >>= 1) {
            #pragma unroll
            for (int i = 0; i < RPI; ++i)
                s[i] += __shfl_xor_sync(0xFFFFFFFFu, s[i], o);
        }

        float cm = fmaxf(fmaxf(s[0] + bias, s[1] + bias),
                         fmaxf(s[2] + bias, s[3] + bias));
        const float m_new = fmaxf(m, cm);
        const float scale = __expf(m - m_new);
        ssum *= scale;
        acc0.x *= scale; acc0.y *= scale; acc0.z *= scale; acc0.w *= scale;
        acc1.x *= scale; acc1.y *= scale; acc1.z *= scale; acc1.w *= scale;
        m = m_new;

        #pragma unroll
        for (int i = 0; i < RPI; ++i) {
            const float e = __expf(s[i] + bias - m_new);
            ssum += e;
            acc0.x = fmaf(e, h0[i].x, acc0.x);
            acc0.y = fmaf(e, h0[i].y, acc0.y);
            acc0.z = fmaf(e, h0[i].z, acc0.z);
            acc0.w = fmaf(e, h0[i].w, acc0.w);
            // reload h1 from L1 (hit: loaded ~150 cyc ago, default policy)
            const float4* row = H4 + (long)(pos + i) * (DIM / 4);
            float4 h1 = row[lane + 32];
            acc1.x = fmaf(e, h1.x, acc1.x);
            acc1.y = fmaf(e, h1.y, acc1.y);
            acc1.z = fmaf(e, h1.z, acc1.z);
            acc1.w = fmaf(e, h1.w, acc1.w);
        }
    }

    // ---- guarded tail: 1..RPI-1 rows ----
    if (pos < end) {
        const int nr = end - pos;
        float4 h0[RPI];
        float  s[RPI];
        #pragma unroll
        for (int i = 0; i < RPI; ++i) {
            if (i < nr) {
                const float4* row = H4 + (long)(pos + i) * (DIM / 4);
                h0[i] = __ldcs(row + lane);
                float4 h1 = row[lane + 32];
                float d = h0[i].x * w0.x;
                d = fmaf(h0[i].y, w0.y, d);
                d = fmaf(h0[i].z, w0.z, d);
                d = fmaf(h0[i].w, w0.w, d);
                d = fmaf(h1.x, w1.x, d);
                d = fmaf(h1.y, w1.y, d);
                d = fmaf(h1.z, w1.z, d);
                d = fmaf(h1.w, w1.w, d);
                s[i] = d;
            } else {
                h0[i] = make_float4(0.f, 0.f, 0.f, 0.f);
                s[i] = 0.0f;
            }
        }
        #pragma unroll
        for (int o = 16; o > 0; o >>= 1) {
            #pragma unroll
            for (int i = 0; i < RPI; ++i)
                s[i] += __shfl_xor_sync(0xFFFFFFFFu, s[i], o);
        }

        float cm = -INFINITY;
        #pragma unroll
        for (int i = 0; i < RPI; ++i) {
            s[i] = (i < nr) ? (s[i] + bias) : -INFINITY;
            cm = fmaxf(cm, s[i]);
        }
        const float m_new = fmaxf(m, cm);
        const float scale = __expf(m - m_new);
        ssum *= scale;
        acc0.x *= scale; acc0.y *= scale; acc0.z *= scale; acc0.w *= scale;
        acc1.x *= scale; acc1.y *= scale; acc1.z *= scale; acc1.w *= scale;
        m = m_new;

        #pragma unroll
        for (int i = 0; i < RPI; ++i) {
            const float e = __expf(s[i] - m_new);   // 0 for padded rows
            ssum += e;
            acc0.x = fmaf(e, h0[i].x, acc0.x);
            acc0.y = fmaf(e, h0[i].y, acc0.y);
            acc0.z = fmaf(e, h0[i].z, acc0.z);
            acc0.w = fmaf(e, h0[i].w, acc0.w);
            if (i < nr) {
                const float4* row = H4 + (long)(pos + i) * (DIM / 4);
                float4 h1 = row[lane + 32];
                acc1.x = fmaf(e, h1.x, acc1.x);
                acc1.y = fmaf(e, h1.y, acc1.y);
                acc1.z = fmaf(e, h1.z, acc1.z);
                acc1.w = fmaf(e, h1.w, acc1.w);
            }
        }
    }

    const float inv = (ssum > 0.0f) ? (1.0f / ssum) : 0.0f;  // empty -> zeros
    float4 o0 = make_float4(acc0.x * inv, acc0.y * inv, acc0.z * inv, acc0.w * inv);
    float4 o1 = make_float4(acc1.x * inv, acc1.y * inv, acc1.z * inv, acc1.w * inv);
    out4[(long)b * (DIM / 4) + lane]      = o0;
    out4[(long)b * (DIM / 4) + 32 + lane] = o1;
}

extern "C" void kernel_launch(void* const* d_in, const int* in_sizes, int n_in,
                              void* d_out, int out_size) {
    const float* H     = (const float*)d_in[0];
    const int*   batch = (const int*)d_in[1];
    const float* Ww    = (const float*)d_in[2];
    const float* Wb    = (const float*)d_in[3];
    float*       out   = (float*)d_out;
    const int V = in_sizes[1];  // batch[] element count

    int v4 = (V + 3) / 4;
    seg_bounds_scan4<<<(v4 + 255) / 256, 256>>>((const int4*)batch, batch, V);
    agg_warp_kernel<<<NSEG / WPB, 32 * WPB>>>(
        (const float4*)H, (const float4*)Ww, Wb, (float4*)out);
}

// round 7
// speedup vs baseline: 1.0579x; 1.0579x over previous
#include <cuda_runtime.h>
#include <math.h>

#define DIM      256
#define NSEG     32768
#define RPI      4          // rows per iteration (8 independent LDG.128/thread)

// Allocation-free scratch: segment start offsets (batch is sorted).
__device__ int g_seg_start[NSEG + 1];

// Vectorized boundary scan: thread owns 4 consecutive batch entries (int4).
__global__ void seg_bounds_scan4(const int4* __restrict__ batch4,
                                 const int*  __restrict__ batch, int V) {
    int i = blockIdx.x * blockDim.x + threadIdx.x;
    int base = i * 4;
    if (base >= V) return;
    int4 c = batch4[i];
    int prev = (base == 0) ? -1 : batch[base - 1];
    for (int b = prev + 1; b <= c.x; ++b) g_seg_start[b] = base;
    for (int b = c.x  + 1; b <= c.y; ++b) g_seg_start[b] = base + 1;
    for (int b = c.y  + 1; b <= c.z; ++b) g_seg_start[b] = base + 2;
    for (int b = c.z  + 1; b <= c.w; ++b) g_seg_start[b] = base + 3;
    if (base + 4 >= V) {
        for (int b = c.w + 1; b <= NSEG; ++b) g_seg_start[b] = V;
    }
}

// One 32-thread BLOCK (= one warp) per segment: per-warp resource
// retirement kills the Poisson-tail imbalance of multi-warp blocks.
// Single pass over H with online softmax; bias dropped (shift-invariant);
// rescale skipped when the running max doesn't change (warp-uniform branch).
__global__ __launch_bounds__(32)
void agg_warp_kernel(const float4* __restrict__ H4,
                     const float4* __restrict__ Ww4,
                     float4*       __restrict__ out4) {
    const int lane = threadIdx.x;   // 32-thread block == one warp
    const int b    = blockIdx.x;

    const int start = g_seg_start[b];
    const int end   = g_seg_start[b + 1];

    const float4 w0 = Ww4[lane];
    const float4 w1 = Ww4[lane + 32];

    float4 acc0 = make_float4(0.f, 0.f, 0.f, 0.f);
    float4 acc1 = make_float4(0.f, 0.f, 0.f, 0.f);
    float  m    = -INFINITY;
    float  ssum = 0.0f;

    int pos = start;

    // ---- guard-free main loop: full RPI rows ----
    for (; pos + RPI <= end; pos += RPI) {
        float4 h0[RPI], h1[RPI];
        #pragma unroll
        for (int i = 0; i < RPI; ++i) {
            const float4* row = H4 + (long)(pos + i) * (DIM / 4);
            h0[i] = __ldcs(row + lane);
            h1[i] = __ldcs(row + lane + 32);
        }

        float s[RPI];
        #pragma unroll
        for (int i = 0; i < RPI; ++i) {
            float d = h0[i].x * w0.x;
            d = fmaf(h0[i].y, w0.y, d);
            d = fmaf(h0[i].z, w0.z, d);
            d = fmaf(h0[i].w, w0.w, d);
            d = fmaf(h1[i].x, w1.x, d);
            d = fmaf(h1[i].y, w1.y, d);
            d = fmaf(h1[i].z, w1.z, d);
            d = fmaf(h1[i].w, w1.w, d);
            s[i] = d;
        }
        #pragma unroll
        for (int o = 16; o > 0; o >>= 1) {
            #pragma unroll
            for (int i = 0; i < RPI; ++i)
                s[i] += __shfl_xor_sync(0xFFFFFFFFu, s[i], o);
        }

        const float cm = fmaxf(fmaxf(s[0], s[1]), fmaxf(s[2], s[3]));
        if (cm > m) {                         // warp-uniform branch
            const float scale = __expf(m - cm);   // 0 on first iteration
            ssum *= scale;
            acc0.x *= scale; acc0.y *= scale; acc0.z *= scale; acc0.w *= scale;
            acc1.x *= scale; acc1.y *= scale; acc1.z *= scale; acc1.w *= scale;
            m = cm;
        }

        #pragma unroll
        for (int i = 0; i < RPI; ++i) {
            const float e = __expf(s[i] - m);
            ssum += e;
            acc0.x = fmaf(e, h0[i].x, acc0.x);
            acc0.y = fmaf(e, h0[i].y, acc0.y);
            acc0.z = fmaf(e, h0[i].z, acc0.z);
            acc0.w = fmaf(e, h0[i].w, acc0.w);
            acc1.x = fmaf(e, h1[i].x, acc1.x);
            acc1.y = fmaf(e, h1[i].y, acc1.y);
            acc1.z = fmaf(e, h1[i].z, acc1.z);
            acc1.w = fmaf(e, h1[i].w, acc1.w);
        }
    }

    // ---- guarded tail: 1..RPI-1 rows ----
    if (pos < end) {
        const int nr = end - pos;
        float4 h0[RPI], h1[RPI];
        #pragma unroll
        for (int i = 0; i < RPI; ++i) {
            if (i < nr) {
                const float4* row = H4 + (long)(pos + i) * (DIM / 4);
                h0[i] = __ldcs(row + lane);
                h1[i] = __ldcs(row + lane + 32);
            } else {
                h0[i] = make_float4(0.f, 0.f, 0.f, 0.f);
                h1[i] = make_float4(0.f, 0.f, 0.f, 0.f);
            }
        }

        float s[RPI];
        #pragma unroll
        for (int i = 0; i < RPI; ++i) {
            float d = h0[i].x * w0.x;
            d = fmaf(h0[i].y, w0.y, d);
            d = fmaf(h0[i].z, w0.z, d);
            d = fmaf(h0[i].w, w0.w, d);
            d = fmaf(h1[i].x, w1.x, d);
            d = fmaf(h1[i].y, w1.y, d);
            d = fmaf(h1[i].z, w1.z, d);
            d = fmaf(h1[i].w, w1.w, d);
            s[i] = d;
        }
        #pragma unroll
        for (int o = 16; o > 0; o >>= 1) {
            #pragma unroll
            for (int i = 0; i < RPI; ++i)
                s[i] += __shfl_xor_sync(0xFFFFFFFFu, s[i], o);
        }

        float cm = -INFINITY;
        #pragma unroll
        for (int i = 0; i < RPI; ++i) {
            if (i >= nr) s[i] = -INFINITY;
            cm = fmaxf(cm, s[i]);
        }
        if (cm > m) {
            const float scale = __expf(m - cm);
            ssum *= scale;
            acc0.x *= scale; acc0.y *= scale; acc0.z *= scale; acc0.w *= scale;
            acc1.x *= scale; acc1.y *= scale; acc1.z *= scale; acc1.w *= scale;
            m = cm;
        }

        #pragma unroll
        for (int i = 0; i < RPI; ++i) {
            const float e = __expf(s[i] - m);   // 0 for padded rows
            ssum += e;
            acc0.x = fmaf(e, h0[i].x, acc0.x);
            acc0.y = fmaf(e, h0[i].y, acc0.y);
            acc0.z = fmaf(e, h0[i].z, acc0.z);
            acc0.w = fmaf(e, h0[i].w, acc0.w);
            acc1.x = fmaf(e, h1[i].x, acc1.x);
            acc1.y = fmaf(e, h1[i].y, acc1.y);
            acc1.z = fmaf(e, h1[i].z, acc1.z);
            acc1.w = fmaf(e, h1[i].w, acc1.w);
        }
    }

    const float inv = (ssum > 0.0f) ? (1.0f / ssum) : 0.0f;  // empty -> zeros
    float4 o0 = make_float4(acc0.x * inv, acc0.y * inv, acc0.z * inv, acc0.w * inv);
    float4 o1 = make_float4(acc1.x * inv, acc1.y * inv, acc1.z * inv, acc1.w * inv);
    out4[(long)b * (DIM / 4) + lane]      = o0;
    out4[(long)b * (DIM / 4) + 32 + lane] = o1;
}

extern "C" void kernel_launch(void* const* d_in, const int* in_sizes, int n_in,
                              void* d_out, int out_size) {
    const float* H     = (const float*)d_in[0];
    const int*   batch = (const int*)d_in[1];
    const float* Ww    = (const float*)d_in[2];
    float*       out   = (float*)d_out;
    const int V = in_sizes[1];  // batch[] element count

    int v4 = (V + 3) / 4;
    seg_bounds_scan4<<<(v4 + 255) / 256, 256>>>((const int4*)batch, batch, V);
    agg_warp_kernel<<<NSEG, 32>>>(
        (const float4*)H, (const float4*)Ww, (float4*)out);
}